// round 2
// baseline (speedup 1.0000x reference)
#include <cuda_runtime.h>

#define ALPHA 0.01f

// Scratch (static device globals — allocation-free per harness rules)
__device__ float g_h1[32u*64u*112u*112u];   // 102.8 MB: conv1 pooled output [32,64,112,112]
__device__ float g_h2[32u*64u*56u*56u];     //  25.7 MB: conv2 pooled output [32,64,56,56]
__device__ float g_fcp[196*32*10];          // FC split-K partials

// ---------------------------------------------------------------------------
// Kernel 1: conv1(3->64, 3x3, pad1) + leaky + maxpool2  fused
// Grid: (49 tiles, 32 batch), 256 threads. Each thread: 1 pooled pixel, all 64 oc.
// ---------------------------------------------------------------------------
__global__ __launch_bounds__(256) void conv1_kernel(const float* __restrict__ x,
                                                    const float* __restrict__ w1,
                                                    const float* __restrict__ b1)
{
    __shared__ float s_in[3][34][34];   // input tile (+1 halo each side)
    __shared__ float s_w[1728];         // full w1 [oc][c][ky][kx]
    __shared__ float s_b[64];

    const int tid  = threadIdx.x;
    const int t    = blockIdx.x;          // 0..48
    const int b    = blockIdx.y;          // 0..31
    const int tpy0 = (t / 7) * 16;        // pooled tile origin
    const int tpx0 = (t % 7) * 16;
    const int cy0  = tpy0 * 2, cx0 = tpx0 * 2;   // conv-space origin

    for (int i = tid; i < 3*34*34; i += 256) {
        int c  = i / (34*34); int r = i % (34*34);
        int yy = r / 34, xx = r % 34;
        int gy = cy0 - 1 + yy, gx = cx0 - 1 + xx;
        float v = 0.f;
        if (gy >= 0 && gy < 224 && gx >= 0 && gx < 224)
            v = x[((b*3 + c)*224 + gy)*224 + gx];
        s_in[c][yy][xx] = v;
    }
    for (int i = tid; i < 1728; i += 256) s_w[i] = w1[i];
    if (tid < 64) s_b[tid] = b1[tid];
    __syncthreads();

    const int py = tid >> 4, px = tid & 15;       // pooled pixel in tile
    const int ly = py * 2,  lx = px * 2;          // conv-local base

    // 4x4 input patch per channel held in registers (48 regs)
    float p[3][4][4];
    #pragma unroll
    for (int c = 0; c < 3; c++)
        #pragma unroll
        for (int i = 0; i < 4; i++)
            #pragma unroll
            for (int j = 0; j < 4; j++)
                p[c][i][j] = s_in[c][ly+i][lx+j];

    float* outp = &g_h1[((b*64)*112 + (tpy0+py))*112 + (tpx0+px)];
    // 2 output channels per iteration for ILP (8 independent FMA chains)
    for (int oc = 0; oc < 64; oc += 2) {
        const float* wp0 = &s_w[oc*27];
        const float* wp1 = &s_w[(oc+1)*27];
        float b0 = s_b[oc], b1v = s_b[oc+1];
        float a00 = b0,  a01 = b0,  a10 = b0,  a11 = b0;
        float c00 = b1v, c01 = b1v, c10 = b1v, c11 = b1v;
        #pragma unroll
        for (int c = 0; c < 3; c++)
            #pragma unroll
            for (int ky = 0; ky < 3; ky++)
                #pragma unroll
                for (int kx = 0; kx < 3; kx++) {
                    float w0 = wp0[c*9 + ky*3 + kx];   // warp-uniform -> broadcast LDS
                    float w1w = wp1[c*9 + ky*3 + kx];
                    float p00 = p[c][ky  ][kx  ], p01 = p[c][ky  ][kx+1];
                    float p10 = p[c][ky+1][kx  ], p11 = p[c][ky+1][kx+1];
                    a00 += p00 * w0;  a01 += p01 * w0;
                    a10 += p10 * w0;  a11 += p11 * w0;
                    c00 += p00 * w1w; c01 += p01 * w1w;
                    c10 += p10 * w1w; c11 += p11 * w1w;
                }
        // leaky is monotonic: leaky(max) == max(leaky)
        float m0 = fmaxf(fmaxf(a00, a01), fmaxf(a10, a11));
        m0 = m0 > 0.f ? m0 : ALPHA * m0;
        float m1 = fmaxf(fmaxf(c00, c01), fmaxf(c10, c11));
        m1 = m1 > 0.f ? m1 : ALPHA * m1;
        outp[oc*112*112]     = m0;
        outp[(oc+1)*112*112] = m1;
    }
}

// ---------------------------------------------------------------------------
// Kernel 2: conv2(64->64, 3x3, pad1) + leaky + maxpool2  fused  (the hot one)
// Grid: (49 tiles, 32 batch), 256 threads.
// Each thread: 2x2 conv pixels (1 pooled pixel) x 16 oc = 64 fp32 accumulators.
// ic processed in chunks of 8 through smem.
// ---------------------------------------------------------------------------
__global__ __launch_bounds__(256, 2) void conv2_kernel(const float* __restrict__ w2,
                                                       const float* __restrict__ b2)
{
    __shared__ float s_in[8][18][18];   // 10.4 KB
    __shared__ float s_w[8][9][64];     // 18.4 KB, [ic][tap][oc] for float4 oc loads

    const int tid  = threadIdx.x;
    const int t    = blockIdx.x;          // 0..48
    const int b    = blockIdx.y;
    const int tpy0 = (t / 7) * 8;
    const int tpx0 = (t % 7) * 8;
    const int cy0  = tpy0 * 2, cx0 = tpx0 * 2;

    const int ocg = tid & 3, oc0 = ocg * 16;
    const int pix = tid >> 2;
    const int ppy = pix >> 3, ppx = pix & 7;
    const int ly  = ppy * 2, lx = ppx * 2;

    float acc[2][2][16];
    #pragma unroll
    for (int j = 0; j < 16; j++) {
        float bb = b2[oc0 + j];
        acc[0][0][j] = bb; acc[0][1][j] = bb; acc[1][0][j] = bb; acc[1][1][j] = bb;
    }

    for (int ic0 = 0; ic0 < 64; ic0 += 8) {
        for (int i = tid; i < 8*18*18; i += 256) {
            int ic = i / 324; int r = i % 324;
            int yy = r / 18, xx = r % 18;
            int gy = cy0 - 1 + yy, gx = cx0 - 1 + xx;
            float v = 0.f;
            if (gy >= 0 && gy < 112 && gx >= 0 && gx < 112)
                v = g_h1[((b*64 + ic0 + ic)*112 + gy)*112 + gx];
            s_in[ic][yy][xx] = v;
        }
        for (int i = tid; i < 8*9*64; i += 256) {
            int ic = i / 576; int r = i % 576;
            int tap = r / 64, oc = r % 64;
            s_w[ic][tap][oc] = w2[(oc*64 + ic0 + ic)*9 + tap];
        }
        __syncthreads();

        #pragma unroll
        for (int ic = 0; ic < 8; ic++) {
            float p[4][4];
            #pragma unroll
            for (int iy = 0; iy < 4; iy++)
                #pragma unroll
                for (int ix = 0; ix < 4; ix++)
                    p[iy][ix] = s_in[ic][ly+iy][lx+ix];

            #pragma unroll
            for (int ky = 0; ky < 3; ky++)
                #pragma unroll
                for (int kx = 0; kx < 3; kx++) {
                    const float4* wp = (const float4*)&s_w[ic][ky*3 + kx][oc0];
                    float4 w0 = wp[0], w1v = wp[1], w2v = wp[2], w3v = wp[3];
                    float wv[16] = { w0.x, w0.y, w0.z, w0.w,
                                     w1v.x, w1v.y, w1v.z, w1v.w,
                                     w2v.x, w2v.y, w2v.z, w2v.w,
                                     w3v.x, w3v.y, w3v.z, w3v.w };
                    #pragma unroll
                    for (int dy = 0; dy < 2; dy++)
                        #pragma unroll
                        for (int dx = 0; dx < 2; dx++) {
                            float inv = p[ky+dy][kx+dx];
                            #pragma unroll
                            for (int j = 0; j < 16; j++)
                                acc[dy][dx][j] += inv * wv[j];
                        }
                }
        }
        __syncthreads();
    }

    const int oy = tpy0 + ppy, ox = tpx0 + ppx;
    #pragma unroll
    for (int j = 0; j < 16; j++) {
        float m = fmaxf(fmaxf(acc[0][0][j], acc[0][1][j]),
                        fmaxf(acc[1][0][j], acc[1][1][j]));
        m = m > 0.f ? m : ALPHA * m;
        g_h2[((b*64 + oc0 + j)*56 + oy)*56 + ox] = m;
    }
}

// ---------------------------------------------------------------------------
// Kernel 3: FC split-K partials. Grid 196 blocks x 256 threads.
// Each block: one K-chunk of 1024, wfc chunk cached in smem, warp-per-batch.
// ---------------------------------------------------------------------------
__global__ __launch_bounds__(256) void fc_partial_kernel(const float* __restrict__ wfc)
{
    __shared__ float s_w[1024*10];   // 40 KB
    const int tid = threadIdx.x;
    const int k0  = blockIdx.x * 1024;

    for (int i = tid; i < 10240; i += 256) s_w[i] = wfc[k0*10 + i];
    __syncthreads();

    const int warp = tid >> 5, lane = tid & 31;
    for (int bg = 0; bg < 4; bg++) {
        int b = bg*8 + warp;
        float acc[10];
        #pragma unroll
        for (int c = 0; c < 10; c++) acc[c] = 0.f;

        // g_h2 chunk is 16B-aligned (k0 multiple of 1024): use float4 loads
        const float4* hb = (const float4*)&g_h2[b*200704 + k0];
        for (int k4 = lane; k4 < 256; k4 += 32) {
            float4 hv = hb[k4];
            int k = k4 * 4;
            #pragma unroll
            for (int c = 0; c < 10; c++) {
                acc[c] += hv.x * s_w[(k  )*10 + c];
                acc[c] += hv.y * s_w[(k+1)*10 + c];
                acc[c] += hv.z * s_w[(k+2)*10 + c];
                acc[c] += hv.w * s_w[(k+3)*10 + c];
            }
        }
        #pragma unroll
        for (int c = 0; c < 10; c++) {
            #pragma unroll
            for (int off = 16; off; off >>= 1)
                acc[c] += __shfl_xor_sync(0xffffffffu, acc[c], off);
        }
        if (lane == 0) {
            #pragma unroll
            for (int c = 0; c < 10; c++)
                g_fcp[(blockIdx.x*32 + b)*10 + c] = acc[c];
        }
    }
}

// Kernel 4: deterministic final reduction (fixed summation order)
__global__ void fc_reduce_kernel(const float* __restrict__ bfc, float* __restrict__ out)
{
    int tid = threadIdx.x;
    if (tid >= 320) return;
    int b = tid / 10, c = tid % 10;
    float s = bfc[c];
    for (int ch = 0; ch < 196; ch++) s += g_fcp[(ch*32 + b)*10 + c];
    out[b*10 + c] = s;
}

// ---------------------------------------------------------------------------
extern "C" void kernel_launch(void* const* d_in, const int* in_sizes, int n_in,
                              void* d_out, int out_size)
{
    const float* x   = (const float*)d_in[0];
    const float* w1  = (const float*)d_in[1];
    const float* b1  = (const float*)d_in[2];
    const float* w2  = (const float*)d_in[3];
    const float* b2  = (const float*)d_in[4];
    const float* wfc = (const float*)d_in[5];
    const float* bfc = (const float*)d_in[6];
    float* out = (float*)d_out;

    conv1_kernel<<<dim3(49, 32), 256>>>(x, w1, b1);
    conv2_kernel<<<dim3(49, 32), 256>>>(w2, b2);
    fc_partial_kernel<<<196, 256>>>(wfc);
    fc_reduce_kernel<<<1, 320>>>(bfc, out);
}

// round 3
// speedup vs baseline: 1.1038x; 1.1038x over previous
#include <cuda_runtime.h>

#define ALPHA 0.01f

// Scratch (static device globals — allocation-free per harness rules)
__device__ float g_h1[32u*64u*112u*112u];   // 102.8 MB: conv1 pooled output [32,64,112,112]
__device__ float g_h2[32u*64u*56u*56u];     //  25.7 MB: conv2 pooled output [32,64,56,56]
__device__ float g_fcp[196*32*10];          // FC split-K partials

// ---- packed f32x2 helpers (sm_100a; ptxas won't auto-fuse, must use PTX) ----
__device__ __forceinline__ unsigned long long pack2(float x, float y) {
    unsigned long long r;
    asm("mov.b64 %0, {%1, %2};" : "=l"(r) : "f"(x), "f"(y));
    return r;
}
__device__ __forceinline__ unsigned long long ffma2(unsigned long long a,
                                                    unsigned long long b,
                                                    unsigned long long c) {
    unsigned long long d;
    asm("fma.rn.f32x2 %0, %1, %2, %3;" : "=l"(d) : "l"(a), "l"(b), "l"(c));
    return d;
}
__device__ __forceinline__ void unpack2(unsigned long long v, float& x, float& y) {
    asm("mov.b64 {%0, %1}, %2;" : "=f"(x), "=f"(y) : "l"(v));
}
__device__ __forceinline__ float leaky(float v) { return v > 0.f ? v : ALPHA * v; }

// ---------------------------------------------------------------------------
// Kernel 1: conv1(3->64, 3x3, pad1) + leaky + maxpool2, f32x2-packed over oc pairs
// Grid: (49 tiles, 32 batch), 256 threads. Thread: 1 pooled pixel, 64 oc.
// ---------------------------------------------------------------------------
__global__ __launch_bounds__(256) void conv1_kernel(const float* __restrict__ x,
                                                    const float* __restrict__ w1,
                                                    const float* __restrict__ b1)
{
    __shared__ float s_in[3][34][34];                    // input tile (+1 halo)
    __shared__ __align__(16) float s_w2[27][64];         // transposed: [tap][oc]
    __shared__ float s_b[64];

    const int tid  = threadIdx.x;
    const int t    = blockIdx.x;          // 0..48
    const int b    = blockIdx.y;          // 0..31
    const int tpy0 = (t / 7) * 16;
    const int tpx0 = (t % 7) * 16;
    const int cy0  = tpy0 * 2, cx0 = tpx0 * 2;

    for (int i = tid; i < 3*34*34; i += 256) {
        int c  = i / (34*34); int r = i % (34*34);
        int yy = r / 34, xx = r % 34;
        int gy = cy0 - 1 + yy, gx = cx0 - 1 + xx;
        float v = 0.f;
        if (gy >= 0 && gy < 224 && gx >= 0 && gx < 224)
            v = x[((b*3 + c)*224 + gy)*224 + gx];
        s_in[c][yy][xx] = v;
    }
    for (int i = tid; i < 1728; i += 256) {
        int oc = i / 27, tap = i % 27;
        s_w2[tap][oc] = w1[i];
    }
    if (tid < 64) s_b[tid] = b1[tid];
    __syncthreads();

    const int py = tid >> 4, px = tid & 15;
    const int ly = py * 2,  lx = px * 2;

    // 4x4 patch per channel, replicated into both f32x2 lanes
    unsigned long long p2[3][4][4];
    #pragma unroll
    for (int c = 0; c < 3; c++)
        #pragma unroll
        for (int i = 0; i < 4; i++)
            #pragma unroll
            for (int j = 0; j < 4; j++) {
                float v = s_in[c][ly+i][lx+j];
                p2[c][i][j] = pack2(v, v);
            }

    float* outp = &g_h1[((b*64)*112 + (tpy0+py))*112 + (tpx0+px)];
    for (int oc = 0; oc < 64; oc += 2) {
        unsigned long long bb = pack2(s_b[oc], s_b[oc+1]);
        unsigned long long a00 = bb, a01 = bb, a10 = bb, a11 = bb;
        #pragma unroll
        for (int c = 0; c < 3; c++)
            #pragma unroll
            for (int ky = 0; ky < 3; ky++)
                #pragma unroll
                for (int kx = 0; kx < 3; kx++) {
                    int tap = c*9 + ky*3 + kx;
                    // oc-pair of weights, contiguous; warp-uniform -> LDS broadcast
                    unsigned long long w = *(const unsigned long long*)&s_w2[tap][oc];
                    a00 = ffma2(p2[c][ky  ][kx  ], w, a00);
                    a01 = ffma2(p2[c][ky  ][kx+1], w, a01);
                    a10 = ffma2(p2[c][ky+1][kx  ], w, a10);
                    a11 = ffma2(p2[c][ky+1][kx+1], w, a11);
                }
        float v00a, v00b, v01a, v01b, v10a, v10b, v11a, v11b;
        unpack2(a00, v00a, v00b); unpack2(a01, v01a, v01b);
        unpack2(a10, v10a, v10b); unpack2(a11, v11a, v11b);
        // leaky is monotonic: leaky(max) == max(leaky)
        float m0 = fmaxf(fmaxf(v00a, v01a), fmaxf(v10a, v11a));
        float m1 = fmaxf(fmaxf(v00b, v01b), fmaxf(v10b, v11b));
        outp[oc*112*112]     = leaky(m0);
        outp[(oc+1)*112*112] = leaky(m1);
    }
}

// ---------------------------------------------------------------------------
// Kernel 2: conv2(64->64, 3x3, pad1) + leaky + maxpool2  (dominant kernel)
// Grid: (49 tiles, 32 batch), 256 threads.
// Thread: 2x2 conv pixels x 16 oc = 32 f32x2 accumulators (oc-pair packed).
// ---------------------------------------------------------------------------
__global__ __launch_bounds__(256, 2) void conv2_kernel(const float* __restrict__ w2,
                                                       const float* __restrict__ b2)
{
    __shared__ float s_in[8][18][18];                 // 10.4 KB
    __shared__ __align__(16) float s_w[8][9][64];     // 18.4 KB, [ic][tap][oc]

    const int tid  = threadIdx.x;
    const int t    = blockIdx.x;          // 0..48
    const int b    = blockIdx.y;
    const int tpy0 = (t / 7) * 8;
    const int tpx0 = (t % 7) * 8;
    const int cy0  = tpy0 * 2, cx0 = tpx0 * 2;

    const int ocg = tid & 3, oc0 = ocg * 16;
    const int pix = tid >> 2;
    const int ppy = pix >> 3, ppx = pix & 7;
    const int ly  = ppy * 2, lx = ppx * 2;

    unsigned long long acc2[2][2][8];
    #pragma unroll
    for (int j = 0; j < 8; j++) {
        unsigned long long bb = pack2(b2[oc0 + 2*j], b2[oc0 + 2*j + 1]);
        acc2[0][0][j] = bb; acc2[0][1][j] = bb; acc2[1][0][j] = bb; acc2[1][1][j] = bb;
    }

    for (int ic0 = 0; ic0 < 64; ic0 += 8) {
        for (int i = tid; i < 8*18*18; i += 256) {
            int ic = i / 324; int r = i % 324;
            int yy = r / 18, xx = r % 18;
            int gy = cy0 - 1 + yy, gx = cx0 - 1 + xx;
            float v = 0.f;
            if (gy >= 0 && gy < 112 && gx >= 0 && gx < 112)
                v = g_h1[((b*64 + ic0 + ic)*112 + gy)*112 + gx];
            s_in[ic][yy][xx] = v;
        }
        for (int i = tid; i < 8*9*64; i += 256) {
            int ic = i / 576; int r = i % 576;
            int tap = r / 64, oc = r % 64;
            s_w[ic][tap][oc] = w2[(oc*64 + ic0 + ic)*9 + tap];
        }
        __syncthreads();

        #pragma unroll
        for (int ic = 0; ic < 8; ic++) {
            // pack 4x4 input patch, value replicated in both lanes
            unsigned long long p2[4][4];
            #pragma unroll
            for (int iy = 0; iy < 4; iy++)
                #pragma unroll
                for (int ix = 0; ix < 4; ix++) {
                    float v = s_in[ic][ly+iy][lx+ix];
                    p2[iy][ix] = pack2(v, v);
                }

            #pragma unroll
            for (int ky = 0; ky < 3; ky++)
                #pragma unroll
                for (int kx = 0; kx < 3; kx++) {
                    const unsigned long long* wp =
                        (const unsigned long long*)&s_w[ic][ky*3 + kx][oc0];
                    // process oc pairs in two halves of 4 to cap register use
                    #pragma unroll
                    for (int h = 0; h < 2; h++) {
                        unsigned long long w[4];
                        #pragma unroll
                        for (int j = 0; j < 4; j++) w[j] = wp[h*4 + j];
                        #pragma unroll
                        for (int dy = 0; dy < 2; dy++)
                            #pragma unroll
                            for (int dx = 0; dx < 2; dx++) {
                                unsigned long long inv = p2[ky+dy][kx+dx];
                                #pragma unroll
                                for (int j = 0; j < 4; j++)
                                    acc2[dy][dx][h*4+j] = ffma2(w[j], inv, acc2[dy][dx][h*4+j]);
                            }
                    }
                }
        }
        __syncthreads();
    }

    const int oy = tpy0 + ppy, ox = tpx0 + ppx;
    #pragma unroll
    for (int j = 0; j < 8; j++) {
        float e00, o00, e01, o01, e10, o10, e11, o11;
        unpack2(acc2[0][0][j], e00, o00); unpack2(acc2[0][1][j], e01, o01);
        unpack2(acc2[1][0][j], e10, o10); unpack2(acc2[1][1][j], e11, o11);
        float me = fmaxf(fmaxf(e00, e01), fmaxf(e10, e11));
        float mo = fmaxf(fmaxf(o00, o01), fmaxf(o10, o11));
        g_h2[((b*64 + oc0 + 2*j  )*56 + oy)*56 + ox] = leaky(me);
        g_h2[((b*64 + oc0 + 2*j+1)*56 + oy)*56 + ox] = leaky(mo);
    }
}

// ---------------------------------------------------------------------------
// Kernel 3: FC split-K partials. Grid 196 blocks x 256 threads.
// wfc chunk transposed in smem to [c][k] so per-c loads are conflict-free LDS.128.
// ---------------------------------------------------------------------------
__global__ __launch_bounds__(256) void fc_partial_kernel(const float* __restrict__ wfc)
{
    __shared__ __align__(16) float s_wt[10][1024];   // 40 KB
    const int tid = threadIdx.x;
    const int k0  = blockIdx.x * 1024;

    for (int i = tid; i < 10240; i += 256) {
        int k = i / 10, c = i % 10;        // coalesced global read, scattered smem write
        s_wt[c][k] = wfc[k0*10 + i];
    }
    __syncthreads();

    const int warp = tid >> 5, lane = tid & 31;
    for (int bg = 0; bg < 4; bg++) {
        int b = bg*8 + warp;
        float acc[10];
        #pragma unroll
        for (int c = 0; c < 10; c++) acc[c] = 0.f;

        const float4* hb = (const float4*)&g_h2[b*200704 + k0];
        for (int k4 = lane; k4 < 256; k4 += 32) {
            float4 hv = hb[k4];
            #pragma unroll
            for (int c = 0; c < 10; c++) {
                float4 wv = *(const float4*)&s_wt[c][k4*4];   // lane-contiguous LDS.128
                acc[c] += hv.x*wv.x + hv.y*wv.y + hv.z*wv.z + hv.w*wv.w;
            }
        }
        #pragma unroll
        for (int c = 0; c < 10; c++) {
            #pragma unroll
            for (int off = 16; off; off >>= 1)
                acc[c] += __shfl_xor_sync(0xffffffffu, acc[c], off);
        }
        if (lane == 0) {
            #pragma unroll
            for (int c = 0; c < 10; c++)
                g_fcp[(blockIdx.x*32 + b)*10 + c] = acc[c];
        }
    }
}

// ---------------------------------------------------------------------------
// Kernel 4: final reduction. Grid 32 (per batch), 224 threads (7 full warps).
// Deterministic: fixed per-warp shfl order + fixed 7-term smem sum.
// ---------------------------------------------------------------------------
__global__ __launch_bounds__(224) void fc_reduce_kernel(const float* __restrict__ bfc,
                                                        float* __restrict__ out)
{
    __shared__ float s_part[7][10];
    const int tid = threadIdx.x;
    const int b   = blockIdx.x;
    const int warp = tid >> 5, lane = tid & 31;

    float a[10];
    #pragma unroll
    for (int c = 0; c < 10; c++) a[c] = 0.f;

    if (tid < 196) {
        const float2* p = (const float2*)&g_fcp[(tid*32 + b)*10];   // 8B-aligned
        #pragma unroll
        for (int h = 0; h < 5; h++) {
            float2 v = p[h];
            a[2*h]   = v.x;
            a[2*h+1] = v.y;
        }
    }
    #pragma unroll
    for (int c = 0; c < 10; c++) {
        #pragma unroll
        for (int off = 16; off; off >>= 1)
            a[c] += __shfl_xor_sync(0xffffffffu, a[c], off);
    }
    if (lane == 0)
        #pragma unroll
        for (int c = 0; c < 10; c++) s_part[warp][c] = a[c];
    __syncthreads();

    if (tid < 10) {
        float s = bfc[tid];
        #pragma unroll
        for (int w = 0; w < 7; w++) s += s_part[w][tid];
        out[b*10 + tid] = s;
    }
}

// ---------------------------------------------------------------------------
extern "C" void kernel_launch(void* const* d_in, const int* in_sizes, int n_in,
                              void* d_out, int out_size)
{
    const float* x   = (const float*)d_in[0];
    const float* w1  = (const float*)d_in[1];
    const float* b1  = (const float*)d_in[2];
    const float* w2  = (const float*)d_in[3];
    const float* b2  = (const float*)d_in[4];
    const float* wfc = (const float*)d_in[5];
    const float* bfc = (const float*)d_in[6];
    float* out = (float*)d_out;

    conv1_kernel<<<dim3(49, 32), 256>>>(x, w1, b1);
    conv2_kernel<<<dim3(49, 32), 256>>>(w2, b2);
    fc_partial_kernel<<<196, 256>>>(wfc);
    fc_reduce_kernel<<<32, 224>>>(bfc, out);
}